// round 15
// baseline (speedup 1.0000x reference)
#include <cuda_runtime.h>
#include <stdint.h>

// Haar DWT level-1: x (8,32,512,512) fp32 -> (LL,LH,HL,HH) each (8,32,256,256)
// d_out layout: [LL | LH | HL | HH], each band 16,777,216 floats.
//
// FINAL — best measured, repeatably: bench {80.35, 80.35, 80.38, 80.90} us,
// kernel {74.75-76.0} us, DRAM 81-82.4% (6.4-6.5 TB/s). One item per thread,
// 2x LDG.128 + 4x STG.64, block=1024, per-warp rotated band store order,
// default cache policy.
//
// Roofline closure (14 rounds): traffic = 537 MB one-touch floor; DRAM is the
// sole saturated unit at ~82% of 8 TB/s spec = HBM3e mixed-R/W controller
// ceiling. Measured neutral-or-worse: MLP 2/4/8, store width 64/128b, block
// 256/512/1024, occupancy 48-94%, cache policy default/.cs/.wt, persistent
// single-wave grid-stride (-7%: loop-carried dep caps memory queue depth),
// band-spread store order (neutral/equal-best). TMA store path ruled out by
// model: LTS cap is path-independent (~6300 B/cyc), staging adds SMEM traffic
// for identical DRAM behavior.

#define H_IN   512
#define W_IN   512
#define H_OUT  256
#define W_OUT  256
#define N_IMG  256                           // 8*32
#define BAND_ELEMS (N_IMG * H_OUT * W_OUT)   // 16,777,216
#define PAIRS_PER_ROW (W_OUT / 2)            // 128

__global__ __launch_bounds__(1024)
void haar_dwt_kernel(const float* __restrict__ x, float* __restrict__ out) {
    // One thread per (img, oy, px): total = 256*256*128 = 8,388,608.
    unsigned idx = blockIdx.x * blockDim.x + threadIdx.x;

    unsigned px  = idx & (PAIRS_PER_ROW - 1);          // 0..127
    unsigned t   = idx >> 7;                            // img*256 + oy
    unsigned oy  = t & (H_OUT - 1);                     // 0..255
    unsigned img = t >> 8;                              // 0..255

    const float* base = x + ((size_t)img * H_IN + (size_t)(2 * oy)) * W_IN + 4 * px;
    float4 r0 = *reinterpret_cast<const float4*>(base);          // row 2oy
    float4 r1 = *reinterpret_cast<const float4*>(base + W_IN);   // row 2oy+1

    const float q = 0.25f;

    // Pair 0: a=r0.x b=r0.y c=r1.x d=r1.y ; Pair 1: a=r0.z b=r0.w c=r1.z d=r1.w
    float s0a = r0.x + r0.y, s1a = r1.x + r1.y;
    float d0a = r0.y - r0.x, d1a = r1.y - r1.x;
    float s0b = r0.z + r0.w, s1b = r1.z + r1.w;
    float d0b = r0.w - r0.z, d1b = r1.w - r1.z;

    float2 ll = make_float2(q * (s0a + s1a), q * (s0b + s1b));   //  a+b+c+d
    float2 lh = make_float2(q * (s1a - s0a), q * (s1b - s0b));   // -a-b+c+d
    float2 hl = make_float2(q * (d0a + d1a), q * (d0b + d1b));   // -a+b-c+d
    float2 hh = make_float2(q * (d1a - d0a), q * (d1b - d0b));   //  a-b-c+d

    size_t o = ((size_t)img * H_OUT + oy) * PAIRS_PER_ROW + px;

    float2* outp = reinterpret_cast<float2*>(out);
    const size_t band2 = BAND_ELEMS / 2;   // band stride in float2 units

    // Per-warp rotation of band store order (measured equal-best).
    unsigned rot = (threadIdx.x >> 5) & 3;
#pragma unroll
    for (int k = 0; k < 4; k++) {
        unsigned b = (rot + k) & 3;
        float2 v = (b == 0) ? ll : (b == 1) ? lh : (b == 2) ? hl : hh;
        outp[o + (size_t)b * band2] = v;
    }
}

extern "C" void kernel_launch(void* const* d_in, const int* in_sizes, int n_in,
                              void* d_out, int out_size) {
    const float* x = (const float*)d_in[0];
    float* out = (float*)d_out;

    const unsigned total_threads = N_IMG * H_OUT * PAIRS_PER_ROW;  // 8,388,608
    const unsigned block = 1024;
    const unsigned grid = total_threads / block;                   // 8192

    haar_dwt_kernel<<<grid, block>>>(x, out);
}

// round 16
// speedup vs baseline: 1.0052x; 1.0052x over previous
#include <cuda_runtime.h>
#include <stdint.h>

// Haar DWT level-1: x (8,32,512,512) fp32 -> (LL,LH,HL,HH) each (8,32,256,256)
// d_out layout: [LL | LH | HL | HH], each band 16,777,216 floats.
//
// FINAL — best measured, repeatably over 5 identical-binary runs:
// bench {80.35, 80.35, 80.38, 80.80, 80.90} us, kernel {74.75-76.5} us,
// DRAM 80.4-82.4% (6.37-6.53 TB/s). One item per thread, 2x LDG.128 +
// 4x STG.64, block=1024, per-warp rotated band store order, default policy.
//
// Roofline closure (15 rounds): traffic = 537 MB one-touch floor; DRAM is the
// sole saturated unit at ~82% of 8 TB/s spec = HBM3e mixed-R/W controller
// ceiling. Measured neutral-or-worse: MLP 2/4/8, store width 64/128b, block
// 256/512/1024, occupancy 48-94%, cache policy default/.cs/.wt, persistent
// single-wave grid-stride (-7%: loop-carried dep caps memory queue depth),
// band-spread store order (neutral/equal-best). Ruled out by model: TMA store
// staging (LTS cap path-independent), per-CTA R/W phasing (global stream mix
// unchanged at ~2000 resident CTAs; added barriers throttle load queue).

#define H_IN   512
#define W_IN   512
#define H_OUT  256
#define W_OUT  256
#define N_IMG  256                           // 8*32
#define BAND_ELEMS (N_IMG * H_OUT * W_OUT)   // 16,777,216
#define PAIRS_PER_ROW (W_OUT / 2)            // 128

__global__ __launch_bounds__(1024)
void haar_dwt_kernel(const float* __restrict__ x, float* __restrict__ out) {
    // One thread per (img, oy, px): total = 256*256*128 = 8,388,608.
    unsigned idx = blockIdx.x * blockDim.x + threadIdx.x;

    unsigned px  = idx & (PAIRS_PER_ROW - 1);          // 0..127
    unsigned t   = idx >> 7;                            // img*256 + oy
    unsigned oy  = t & (H_OUT - 1);                     // 0..255
    unsigned img = t >> 8;                              // 0..255

    const float* base = x + ((size_t)img * H_IN + (size_t)(2 * oy)) * W_IN + 4 * px;
    float4 r0 = *reinterpret_cast<const float4*>(base);          // row 2oy
    float4 r1 = *reinterpret_cast<const float4*>(base + W_IN);   // row 2oy+1

    const float q = 0.25f;

    // Pair 0: a=r0.x b=r0.y c=r1.x d=r1.y ; Pair 1: a=r0.z b=r0.w c=r1.z d=r1.w
    float s0a = r0.x + r0.y, s1a = r1.x + r1.y;
    float d0a = r0.y - r0.x, d1a = r1.y - r1.x;
    float s0b = r0.z + r0.w, s1b = r1.z + r1.w;
    float d0b = r0.w - r0.z, d1b = r1.w - r1.z;

    float2 ll = make_float2(q * (s0a + s1a), q * (s0b + s1b));   //  a+b+c+d
    float2 lh = make_float2(q * (s1a - s0a), q * (s1b - s0b));   // -a-b+c+d
    float2 hl = make_float2(q * (d0a + d1a), q * (d0b + d1b));   // -a+b-c+d
    float2 hh = make_float2(q * (d1a - d0a), q * (d1b - d0b));   //  a-b-c+d

    size_t o = ((size_t)img * H_OUT + oy) * PAIRS_PER_ROW + px;

    float2* outp = reinterpret_cast<float2*>(out);
    const size_t band2 = BAND_ELEMS / 2;   // band stride in float2 units

    // Per-warp rotation of band store order (measured equal-best).
    unsigned rot = (threadIdx.x >> 5) & 3;
#pragma unroll
    for (int k = 0; k < 4; k++) {
        unsigned b = (rot + k) & 3;
        float2 v = (b == 0) ? ll : (b == 1) ? lh : (b == 2) ? hl : hh;
        outp[o + (size_t)b * band2] = v;
    }
}

extern "C" void kernel_launch(void* const* d_in, const int* in_sizes, int n_in,
                              void* d_out, int out_size) {
    const float* x = (const float*)d_in[0];
    float* out = (float*)d_out;

    const unsigned total_threads = N_IMG * H_OUT * PAIRS_PER_ROW;  // 8,388,608
    const unsigned block = 1024;
    const unsigned grid = total_threads / block;                   // 8192

    haar_dwt_kernel<<<grid, block>>>(x, out);
}

// round 17
// speedup vs baseline: 1.0056x; 1.0004x over previous
#include <cuda_runtime.h>
#include <stdint.h>

// Haar DWT level-1: x (8,32,512,512) fp32 -> (LL,LH,HL,HH) each (8,32,256,256)
// d_out layout: [LL | LH | HL | HH], each band 16,777,216 floats.
//
// FINAL — best measured, repeatably over 6 identical-binary runs:
// bench {80.35, 80.35, 80.38, 80.38, 80.80, 80.90} us, kernel {74.6-76.5} us,
// DRAM 80.4-82.5% (6.37-6.54 TB/s). One item per thread, 2x LDG.128 +
// 4x STG.64, block=1024, per-warp rotated band store order, default policy.
//
// Roofline closure (16 rounds): traffic = 537 MB one-touch floor; DRAM is the
// sole saturated unit at ~82% of 8 TB/s spec = HBM3e mixed-R/W controller
// ceiling. Measured neutral-or-worse: MLP 2/4/8, store width 64/128b, block
// 256/512/1024, occupancy 48-94%, cache policy default/.cs/.wt, persistent
// single-wave grid-stride (-7%: loop-carried dep caps memory queue depth),
// band-spread store order (neutral/equal-best). Ruled out by model: TMA store
// staging (LTS cap path-independent), per-CTA R/W phasing (global stream mix
// unchanged at ~2000 resident CTAs; added barriers throttle load queue).

#define H_IN   512
#define W_IN   512
#define H_OUT  256
#define W_OUT  256
#define N_IMG  256                           // 8*32
#define BAND_ELEMS (N_IMG * H_OUT * W_OUT)   // 16,777,216
#define PAIRS_PER_ROW (W_OUT / 2)            // 128

__global__ __launch_bounds__(1024)
void haar_dwt_kernel(const float* __restrict__ x, float* __restrict__ out) {
    // One thread per (img, oy, px): total = 256*256*128 = 8,388,608.
    unsigned idx = blockIdx.x * blockDim.x + threadIdx.x;

    unsigned px  = idx & (PAIRS_PER_ROW - 1);          // 0..127
    unsigned t   = idx >> 7;                            // img*256 + oy
    unsigned oy  = t & (H_OUT - 1);                     // 0..255
    unsigned img = t >> 8;                              // 0..255

    const float* base = x + ((size_t)img * H_IN + (size_t)(2 * oy)) * W_IN + 4 * px;
    float4 r0 = *reinterpret_cast<const float4*>(base);          // row 2oy
    float4 r1 = *reinterpret_cast<const float4*>(base + W_IN);   // row 2oy+1

    const float q = 0.25f;

    // Pair 0: a=r0.x b=r0.y c=r1.x d=r1.y ; Pair 1: a=r0.z b=r0.w c=r1.z d=r1.w
    float s0a = r0.x + r0.y, s1a = r1.x + r1.y;
    float d0a = r0.y - r0.x, d1a = r1.y - r1.x;
    float s0b = r0.z + r0.w, s1b = r1.z + r1.w;
    float d0b = r0.w - r0.z, d1b = r1.w - r1.z;

    float2 ll = make_float2(q * (s0a + s1a), q * (s0b + s1b));   //  a+b+c+d
    float2 lh = make_float2(q * (s1a - s0a), q * (s1b - s0b));   // -a-b+c+d
    float2 hl = make_float2(q * (d0a + d1a), q * (d0b + d1b));   // -a+b-c+d
    float2 hh = make_float2(q * (d1a - d0a), q * (d1b - d0b));   //  a-b-c+d

    size_t o = ((size_t)img * H_OUT + oy) * PAIRS_PER_ROW + px;

    float2* outp = reinterpret_cast<float2*>(out);
    const size_t band2 = BAND_ELEMS / 2;   // band stride in float2 units

    // Per-warp rotation of band store order (measured equal-best).
    unsigned rot = (threadIdx.x >> 5) & 3;
#pragma unroll
    for (int k = 0; k < 4; k++) {
        unsigned b = (rot + k) & 3;
        float2 v = (b == 0) ? ll : (b == 1) ? lh : (b == 2) ? hl : hh;
        outp[o + (size_t)b * band2] = v;
    }
}

extern "C" void kernel_launch(void* const* d_in, const int* in_sizes, int n_in,
                              void* d_out, int out_size) {
    const float* x = (const float*)d_in[0];
    float* out = (float*)d_out;

    const unsigned total_threads = N_IMG * H_OUT * PAIRS_PER_ROW;  // 8,388,608
    const unsigned block = 1024;
    const unsigned grid = total_threads / block;                   // 8192

    haar_dwt_kernel<<<grid, block>>>(x, out);
}